// round 4
// baseline (speedup 1.0000x reference)
#include <cuda_runtime.h>
#include <math.h>

#define HID    1024
#define GATES  4096
#define LATENT 2048
#define SEQ    16

// ---------------- device scratch (no allocation allowed) ----------------
__device__ float g_xg[SEQ * GATES];   // pre-activation gates for current layer
__device__ float g_h1[SEQ * HID];     // layer-0 hidden outputs (per-step rows)
__device__ float g_c[HID];            // cell state (reset via first-step flag)

__device__ __forceinline__ float sigmoidf_(float x) {
    return 1.0f / (1.0f + __expf(-x));
}

// ---------------- batched input GEMM kernel --------------------------------
// out[t][row] = inp[t] . W[row] + b1[row] + b2[row]
// grid = 128 CTAs x 256 thr; warp (blockIdx*8+warp) owns rows 4q..4q+3.
// inp (SEQ x D) staged in SMEM; W (GATES x D) streamed once from HBM/L2.
template <int D>
__global__ void __launch_bounds__(256, 1)
gate_gemm_kernel(const float* __restrict__ W,
                 const float* __restrict__ inp,
                 const float* __restrict__ b1,
                 const float* __restrict__ b2,
                 float* __restrict__ out) {
    extern __shared__ float smem[];
    const int tid  = threadIdx.x;
    const int lane = tid & 31;
    const int warp = tid >> 5;
    const int NF4  = D / 4;

    for (int i = tid; i < SEQ * D; i += 256) smem[i] = inp[i];
    __syncthreads();
    const float4* xs4 = (const float4*)smem;

    const int row = (blockIdx.x * 8 + warp) * 4;

    float acc[4][SEQ];
#pragma unroll
    for (int r = 0; r < 4; r++)
#pragma unroll
        for (int t = 0; t < SEQ; t++) acc[r][t] = 0.0f;

    const float4* w0 = (const float4*)(W + (size_t)(row + 0) * D);
    const float4* w1 = (const float4*)(W + (size_t)(row + 1) * D);
    const float4* w2 = (const float4*)(W + (size_t)(row + 2) * D);
    const float4* w3 = (const float4*)(W + (size_t)(row + 3) * D);

    for (int ci = lane; ci < NF4; ci += 32) {
        float4 a0 = w0[ci], a1 = w1[ci], a2 = w2[ci], a3 = w3[ci];
#pragma unroll
        for (int t = 0; t < SEQ; t++) {
            float4 xv = xs4[t * NF4 + ci];
            acc[0][t] += a0.x * xv.x + a0.y * xv.y + a0.z * xv.z + a0.w * xv.w;
            acc[1][t] += a1.x * xv.x + a1.y * xv.y + a1.z * xv.z + a1.w * xv.w;
            acc[2][t] += a2.x * xv.x + a2.y * xv.y + a2.z * xv.z + a2.w * xv.w;
            acc[3][t] += a3.x * xv.x + a3.y * xv.y + a3.z * xv.z + a3.w * xv.w;
        }
    }
#pragma unroll
    for (int r = 0; r < 4; r++) {
#pragma unroll
        for (int t = 0; t < SEQ; t++) {
            float s = acc[r][t];
#pragma unroll
            for (int off = 16; off; off >>= 1)
                s += __shfl_xor_sync(0xffffffffu, s, off);
            if (lane == 0)
                out[t * GATES + row + r] = s + b1[row + r] + b2[row + r];
        }
    }
}

// ---------------- one LSTM timestep ----------------------------------------
// grid = 256 CTAs x 128 thr. Warp (blockIdx*4+warp) owns hidden unit j:
// computes the 4 gate dot products h_{t-1} . w_hh[g*HID+j], then lane 0 does
// the pointwise cell update. h_prev is a distinct buffer written by the
// PREVIOUS LAUNCH -> no races by construction. c[j] is RMW'd by the same
// thread across launches.
__global__ void __launch_bounds__(128, 8)
lstm_step_kernel(const float* __restrict__ w_hh,
                 const float* __restrict__ xg_t,
                 const float* __restrict__ h_prev,   // null iff first
                 float* __restrict__ c_state,
                 float* __restrict__ h_out,
                 float* __restrict__ last_out,       // null unless t == SEQ-1
                 int first) {
    const int lane = threadIdx.x & 31;
    const int warp = threadIdx.x >> 5;
    const int j    = blockIdx.x * 4 + warp;

    float dot[4] = {0.f, 0.f, 0.f, 0.f};
    if (!first) {
        const float4* h4 = (const float4*)h_prev;
        float4 hv[8];
#pragma unroll
        for (int q = 0; q < 8; q++) hv[q] = h4[lane + 32 * q];
#pragma unroll
        for (int g = 0; g < 4; g++) {
            const float4* wr = (const float4*)(w_hh + (size_t)(g * HID + j) * HID);
            float s = 0.0f;
#pragma unroll
            for (int q = 0; q < 8; q++) {
                float4 w = wr[lane + 32 * q];
                s += w.x * hv[q].x + w.y * hv[q].y + w.z * hv[q].z + w.w * hv[q].w;
            }
#pragma unroll
            for (int off = 16; off; off >>= 1)
                s += __shfl_xor_sync(0xffffffffu, s, off);
            dot[g] = s;
        }
    }

    if (lane == 0) {
        float gi = xg_t[0 * HID + j] + dot[0];
        float gf = xg_t[1 * HID + j] + dot[1];
        float gg = xg_t[2 * HID + j] + dot[2];
        float go = xg_t[3 * HID + j] + dot[3];
        float iv = sigmoidf_(gi);
        float fv = sigmoidf_(gf);
        float gv = tanhf(gg);
        float ov = sigmoidf_(go);
        float cprev = first ? 0.0f : c_state[j];
        float cn = fv * cprev + iv * gv;
        c_state[j] = cn;
        float hval = ov * tanhf(cn);
        h_out[j] = hval;
        if (last_out) last_out[j] = hval;
    }
}

// ---------------- host-side launch sequence (graph-capturable) -------------
extern "C" void kernel_launch(void* const* d_in, const int* in_sizes, int n_in,
                              void* d_out, int out_size) {
    const float* x     = (const float*)d_in[0];
    const float* w_ih0 = (const float*)d_in[1];
    const float* w_hh0 = (const float*)d_in[2];
    const float* b_ih0 = (const float*)d_in[3];
    const float* b_hh0 = (const float*)d_in[4];
    const float* w_ih1 = (const float*)d_in[5];
    const float* w_hh1 = (const float*)d_in[6];
    const float* b_ih1 = (const float*)d_in[7];
    const float* b_hh1 = (const float*)d_in[8];
    float* out = (float*)d_out;   // [0:HID) = last_output, [HID:) = h2 rows

    float *xg, *h1, *c;
    cudaGetSymbolAddress((void**)&xg, g_xg);
    cudaGetSymbolAddress((void**)&h1, g_h1);
    cudaGetSymbolAddress((void**)&c,  g_c);

    cudaFuncSetAttribute(gate_gemm_kernel<LATENT>,
                         cudaFuncAttributeMaxDynamicSharedMemorySize,
                         SEQ * LATENT * 4);
    cudaFuncSetAttribute(gate_gemm_kernel<HID>,
                         cudaFuncAttributeMaxDynamicSharedMemorySize,
                         SEQ * HID * 4);

    // Layer 0: xg = x @ w_ih0^T + b_ih0 + b_hh0, then 16 recurrent steps
    gate_gemm_kernel<LATENT><<<128, 256, SEQ * LATENT * 4>>>(
        w_ih0, x, b_ih0, b_hh0, xg);
    for (int t = 0; t < SEQ; t++) {
        lstm_step_kernel<<<256, 128>>>(
            w_hh0, xg + t * GATES,
            (t == 0) ? nullptr : (h1 + (t - 1) * HID),
            c, h1 + t * HID, nullptr, t == 0 ? 1 : 0);
    }

    // Layer 1: xg = h1 @ w_ih1^T + b_ih1 + b_hh1, then 16 recurrent steps
    gate_gemm_kernel<HID><<<128, 256, SEQ * HID * 4>>>(
        w_ih1, h1, b_ih1, b_hh1, xg);
    float* h2 = out + HID;
    for (int t = 0; t < SEQ; t++) {
        lstm_step_kernel<<<256, 128>>>(
            w_hh1, xg + t * GATES,
            (t == 0) ? nullptr : (h2 + (t - 1) * HID),
            c, h2 + t * HID,
            (t == SEQ - 1) ? out : nullptr, t == 0 ? 1 : 0);
    }
}